// round 15
// baseline (speedup 1.0000x reference)
#include <cuda_runtime.h>
#include <cuda_fp16.h>
#include <cstdint>

#define S_LEN    2048
#define L        50
#define TILE     122
#define RROWS    128
#define NTHREADS 256
#define NTILES   ((S_LEN + TILE - 1) / TILE)   // 17

// K packing: left msg k 0..49, right msg k 56..105, K=112 (7 ks of 16)
#define NKS 7

// smem byte offsets from 1024-aligned base
#define OFF_AHI 0u          // A hi frags: 8 rb x 7 ks x 32 lanes x uint4 = 28672
#define OFF_ALO 28672u
#define OFF_BH  57344u      // B hi frags: 7 nt x 7 ks x 32 lanes x uint2 = 12544
#define OFF_MSK 69888u
#define OFF_TS  70400u
#define OFF_TE  70656u
#define SMEM_BYTES (70912 + 1024)

__device__ __forceinline__ uint32_t hpack(float e0, float e1) {
    uint32_t r;
    asm("cvt.rn.f16x2.f32 %0, %1, %2;" : "=r"(r) : "f"(e1), "f"(e0));
    return r;   // lower half = e0, upper = e1
}
__device__ __forceinline__ float hhi(float v) {
    return __half2float(__float2half_rn(v));
}
__device__ __forceinline__ void mma16(float* d, uint32_t a0, uint32_t a1,
                                      uint32_t a2, uint32_t a3,
                                      uint32_t b0, uint32_t b1) {
    asm volatile(
        "mma.sync.aligned.m16n8k16.row.col.f32.f16.f16.f32 "
        "{%0,%1,%2,%3}, {%4,%5,%6,%7}, {%8,%9}, {%0,%1,%2,%3};"
        : "+f"(d[0]), "+f"(d[1]), "+f"(d[2]), "+f"(d[3])
        : "r"(a0), "r"(a1), "r"(a2), "r"(a3), "r"(b0), "r"(b1));
}

// word index (uint32) of A-fragment word (row, w); c-slot XOR-swizzled by
// (rr&7)>>1 so warp-wide frag stores are bank-conflict-free.
__device__ __forceinline__ int fragidx(int row, int w) {
    int rb = row >> 4, rr = row & 15;
    int ks = w >> 3, win = w & 7, tI = win & 3;
    int c  = ((win >= 4) ? 2 : 0) + ((rr >= 8) ? 1 : 0);
    int cx = c ^ (((rr & 7) >> 1) & 3);
    return (((rb * NKS + ks) * 32) + (rr & 7) * 4 + tI) * 4 + cx;
}

__global__ __launch_bounds__(NTHREADS, 3) void mfvi_kernel(
    const float* __restrict__ unary,
    const float* __restrict__ mask,
    const float* __restrict__ Tg,
    const float* __restrict__ tstart,
    const float* __restrict__ tend,
    float* __restrict__ out)
{
    extern __shared__ char dsm_raw[];
    char* smp = (char*)(((uintptr_t)dsm_raw + 1023) & ~(uintptr_t)1023);
    uint32_t* AhiU = (uint32_t*)(smp + OFF_AHI);
    uint32_t* AloU = (uint32_t*)(smp + OFF_ALO);
    uint2*    BH   = (uint2*)   (smp + OFF_BH);
    float*    Msk  = (float*)   (smp + OFF_MSK);
    float*    Tss  = (float*)   (smp + OFF_TS);
    float*    Tes  = (float*)   (smp + OFF_TE);

    const int n    = blockIdx.y;
    const int p0   = blockIdx.x * TILE;
    const int base = p0 - 3;
    const int tid  = threadIdx.x;
    const int w    = tid >> 5;            // warp = row-block 0..7
    const int l    = tid & 31;
    const int gID  = l >> 2;
    const int tID  = l & 3;
    const int r    = 16 * w + gID;        // this lane's first row
    const int r8   = r + 8;               // second row
    const int ga   = base + r;
    const int gb   = base + r8;
    const bool vA  = (ga >= 0) && (ga < S_LEN);
    const bool vB  = (gb >= 0) && (gb < S_LEN);
    const float* uA = unary + ((size_t)n * S_LEN + (vA ? ga : 0)) * L;
    const float* uB = unary + ((size_t)n * S_LEN + (vB ? gb : 0)) * L;
    const bool x1  = (gID >> 1) & 1;      // load-side unpermute controls
    const bool x2  = (gID >> 2) & 1;

    // ---- prologue: zero A hi+lo frag regions (never-written words must be 0) ----
    {
        float4 z = make_float4(0.f, 0.f, 0.f, 0.f);
        for (int i = tid; i < (int)(2 * 28672 / 16); i += NTHREADS)
            ((float4*)(smp + OFF_AHI))[i] = z;
    }
    // ---- B hi fragments (fp16), m16n8k16 col-major fragment order ----
    // B'[bn][k]: k<50 -> T[k][bn] ; 56<=k<106 -> T[bn][k-56] ; else 0
    for (int idx = tid; idx < 7 * NKS * 32; idx += NTHREADS) {
        int lane = idx & 31, rem = idx >> 5;
        int ks = rem % NKS, nt = rem / NKS;
        int gI = lane >> 2, tI = lane & 3;
        int bn = nt * 8 + gI;
        int k0 = 16 * ks + 2 * tI;
        float v[4];
        #pragma unroll
        for (int h = 0; h < 4; h++) {
            int k = k0 + (h >> 1) * 8 + (h & 1);
            float val = 0.f;
            if (bn < L) {
                if (k < L)                        val = Tg[k * L + bn];
                else if (k >= 56 && k < 56 + L)   val = Tg[bn * L + (k - 56)];
            }
            v[h] = val;
        }
        BH[(nt * NKS + ks) * 32 + lane] = make_uint2(hpack(v[0], v[1]), hpack(v[2], v[3]));
    }
    if (tid < RROWS) {
        int g = base + tid;
        Msk[tid] = (g >= 0 && g < S_LEN) ? mask[(size_t)n * S_LEN + g] : 0.f;
    }
    if (tid < 64) {
        Tss[tid] = (tid < L) ? tstart[tid] : 0.f;
        Tes[tid] = (tid < L) ? tend[tid]   : 0.f;
    }
    __syncthreads();

    float acc[7][4];   // [nt]: {row r c0, row r c1, row r8 c0, row r8 c1}

    #pragma unroll 1
    for (int it = 0; it <= 3; it++) {
        const bool actA = vA && (r  >= it) && (r  < RROWS - it);
        const bool actB = vB && (r8 >= it) && (r8 < RROWS - it);

        // ==== combine: acc = (u*m + D + bnd) * m   (acc holds D from last MMA) ====
        {
            const float ma = Msk[r], mb = Msk[r8];
            #pragma unroll
            for (int nt = 0; nt < 7; nt++) {
                const int c0 = 8 * nt + 2 * tID;
                if (c0 < L) {
                    float2 ua = vA ? *(const float2*)&uA[c0] : make_float2(0.f, 0.f);
                    float2 ub = vB ? *(const float2*)&uB[c0] : make_float2(0.f, 0.f);
                    if (it == 0) {
                        acc[nt][0] = ua.x * ma; acc[nt][1] = ua.y * ma;
                        acc[nt][2] = ub.x * mb; acc[nt][3] = ub.y * mb;
                    } else {
                        float2 ba = (ga == 0) ? *(const float2*)&Tss[c0]
                                              : *(const float2*)&Tes[c0];
                        float2 bb = *(const float2*)&Tes[c0];   // gb==0 impossible (r8>=8)
                        acc[nt][0] = (ua.x * ma + acc[nt][0] + ba.x) * ma;
                        acc[nt][1] = (ua.y * ma + acc[nt][1] + ba.y) * ma;
                        acc[nt][2] = (ub.x * mb + acc[nt][2] + bb.x) * mb;
                        acc[nt][3] = (ub.y * mb + acc[nt][3] + bb.y) * mb;
                    }
                }
            }
        }

        if (it == 3) {
            // ==== final write to global ====
            #pragma unroll
            for (int nt = 0; nt < 7; nt++) {
                const int c0 = 8 * nt + 2 * tID;
                if (c0 < L) {
                    if (actA)
                        *(float2*)&out[((size_t)n * S_LEN + ga) * L + c0] =
                            make_float2(acc[nt][0], acc[nt][1]);
                    if (actB)
                        *(float2*)&out[((size_t)n * S_LEN + gb) * L + c0] =
                            make_float2(acc[nt][2], acc[nt][3]);
                }
            }
            break;
        }

        // ==== softmax per row via quad shuffles ====
        {
            float mxa = -3.4e38f, mxb = -3.4e38f;
            #pragma unroll
            for (int nt = 0; nt < 7; nt++) {
                const int c0 = 8 * nt + 2 * tID;
                if (c0 < L) {
                    mxa = fmaxf(mxa, fmaxf(acc[nt][0], acc[nt][1]));
                    mxb = fmaxf(mxb, fmaxf(acc[nt][2], acc[nt][3]));
                }
            }
            mxa = fmaxf(mxa, __shfl_xor_sync(0xffffffffu, mxa, 1));
            mxb = fmaxf(mxb, __shfl_xor_sync(0xffffffffu, mxb, 1));
            mxa = fmaxf(mxa, __shfl_xor_sync(0xffffffffu, mxa, 2));
            mxb = fmaxf(mxb, __shfl_xor_sync(0xffffffffu, mxb, 2));
            float sa = 0.f, sb = 0.f;
            #pragma unroll
            for (int nt = 0; nt < 7; nt++) {
                const int c0 = 8 * nt + 2 * tID;
                if (c0 < L) {
                    acc[nt][0] = __expf(acc[nt][0] - mxa);
                    acc[nt][1] = __expf(acc[nt][1] - mxa);
                    acc[nt][2] = __expf(acc[nt][2] - mxb);
                    acc[nt][3] = __expf(acc[nt][3] - mxb);
                    sa += acc[nt][0] + acc[nt][1];
                    sb += acc[nt][2] + acc[nt][3];
                }
            }
            sa += __shfl_xor_sync(0xffffffffu, sa, 1);
            sb += __shfl_xor_sync(0xffffffffu, sb, 1);
            sa += __shfl_xor_sync(0xffffffffu, sa, 2);
            sb += __shfl_xor_sync(0xffffffffu, sb, 2);
            float ia = __fdividef(1.f, sa);
            float ib = __fdividef(1.f, sb);

            // ==== write A-fragments (hi/lo fp16, swizzled slots) for next MMA ====
            #pragma unroll
            for (int nt = 0; nt < 7; nt++) {
                const int c0 = 8 * nt + 2 * tID;
                if (c0 < L) {
                    const int wd = 4 * nt + tID;
                    if (actA) {
                        float p0v = acc[nt][0] * ia, p1v = acc[nt][1] * ia;
                        uint32_t ph = hpack(p0v, p1v);
                        uint32_t pl = hpack(p0v - hhi(p0v), p1v - hhi(p1v));
                        if (r + 1 < RROWS) {
                            int ix = fragidx(r + 1, wd);
                            AhiU[ix] = ph;  AloU[ix] = pl;
                        }
                        if (r - 1 >= 0) {
                            int ix = fragidx(r - 1, 28 + wd);
                            AhiU[ix] = ph;  AloU[ix] = pl;
                        }
                    }
                    if (actB) {
                        float p0v = acc[nt][2] * ib, p1v = acc[nt][3] * ib;
                        uint32_t ph = hpack(p0v, p1v);
                        uint32_t pl = hpack(p0v - hhi(p0v), p1v - hhi(p1v));
                        if (r8 + 1 < RROWS) {
                            int ix = fragidx(r8 + 1, wd);
                            AhiU[ix] = ph;  AloU[ix] = pl;
                        }
                        {                                   // r8-1 >= 7 always
                            int ix = fragidx(r8 - 1, 28 + wd);
                            AhiU[ix] = ph;  AloU[ix] = pl;
                        }
                    }
                }
            }
        }
        __syncthreads();

        // ==== MMA: warp w = rows [16w,16w+16), all 7 col-groups, fp16 2-split ====
        {
            #pragma unroll
            for (int nt = 0; nt < 7; nt++)
                #pragma unroll
                for (int j = 0; j < 4; j++) acc[nt][j] = 0.f;

            const uint4* Ah4 = (const uint4*)(smp + OFF_AHI);
            const uint4* Al4 = (const uint4*)(smp + OFF_ALO);
            #pragma unroll
            for (int ks = 0; ks < NKS; ks++) {
                uint4 vh = Ah4[(w * NKS + ks) * 32 + l];
                uint4 vl = Al4[(w * NKS + ks) * 32 + l];
                // unpermute: logical[i] = phys[i ^ x]  (x = (l>>3)&3)
                uint32_t ha = vh.x, hb = vh.y, hc = vh.z, hd = vh.w;
                uint32_t la = vl.x, lb = vl.y, lc = vl.z, ld = vl.w;
                if (x1) { uint32_t t;
                    t = ha; ha = hb; hb = t;  t = hc; hc = hd; hd = t;
                    t = la; la = lb; lb = t;  t = lc; lc = ld; ld = t; }
                if (x2) { uint32_t t;
                    t = ha; ha = hc; hc = t;  t = hb; hb = hd; hd = t;
                    t = la; la = lc; lc = t;  t = lb; lb = ld; ld = t; }
                #pragma unroll
                for (int nt = 0; nt < 7; nt++) {
                    uint2 b = BH[(nt * NKS + ks) * 32 + l];
                    mma16(acc[nt], ha, hb, hc, hd, b.x, b.y);
                    mma16(acc[nt], la, lb, lc, ld, b.x, b.y);
                }
            }
        }
        __syncthreads();
    }
}

extern "C" void kernel_launch(void* const* d_in, const int* in_sizes, int n_in,
                              void* d_out, int out_size)
{
    const float* unary = (const float*)d_in[0];
    const float* mask  = (const float*)d_in[1];
    const float* T     = (const float*)d_in[2];
    const float* ts    = (const float*)d_in[3];
    const float* te    = (const float*)d_in[4];
    (void)n_in; (void)out_size;

    cudaFuncSetAttribute(mfvi_kernel,
                         cudaFuncAttributeMaxDynamicSharedMemorySize, SMEM_BYTES);

    int NS = in_sizes[1];
    int N  = NS / S_LEN;
    dim3 grid(NTILES, N);
    mfvi_kernel<<<grid, NTHREADS, SMEM_BYTES>>>(unary, mask, T, ts, te, (float*)d_out);
}

// round 16
// speedup vs baseline: 1.0150x; 1.0150x over previous
#include <cuda_runtime.h>
#include <cuda_fp16.h>
#include <cstdint>

#define S_LEN    2048
#define L        50
#define TILE     122
#define RROWS    128
#define NTHREADS 256
#define NTILES   ((S_LEN + TILE - 1) / TILE)   // 17

// K packing: left msg k 0..49, right msg k 56..105, K=112 (7 ks of 16)
#define NKS 7
#define PLW 1792    // words per A plane: 8 rb x 7 ks x 32

// smem byte offsets from 1024-aligned base
#define OFF_AHI 0u          // A hi frags: 4 planes x 1792 words = 28672 B
#define OFF_ALO 28672u
#define OFF_BH  57344u      // B hi frags: 7 nt x 7 ks x 32 lanes x uint2 = 12544
#define OFF_MSK 69888u
#define OFF_TS  70400u
#define OFF_TE  70656u
#define SMEM_BYTES (70912 + 1024)

__device__ __forceinline__ uint32_t hpack(float e0, float e1) {
    uint32_t r;
    asm("cvt.rn.f16x2.f32 %0, %1, %2;" : "=r"(r) : "f"(e1), "f"(e0));
    return r;   // lower half = e0, upper = e1
}
__device__ __forceinline__ float hhi(float v) {
    return __half2float(__float2half_rn(v));
}
__device__ __forceinline__ void mma16(float* d, uint32_t a0, uint32_t a1,
                                      uint32_t a2, uint32_t a3,
                                      uint32_t b0, uint32_t b1) {
    asm volatile(
        "mma.sync.aligned.m16n8k16.row.col.f32.f16.f16.f32 "
        "{%0,%1,%2,%3}, {%4,%5,%6,%7}, {%8,%9}, {%0,%1,%2,%3};"
        : "+f"(d[0]), "+f"(d[1]), "+f"(d[2]), "+f"(d[3])
        : "r"(a0), "r"(a1), "r"(a2), "r"(a3), "r"(b0), "r"(b1));
}

// A-fragment plane-split addressing: component c of (row, logical word w)
// lives in plane c at word (rb*NKS+ks)*32 + (rr&7)*4 + tI.
__device__ __forceinline__ int fragword(int row, int wd) {
    int rb = row >> 4, rr = row & 15;
    int ks = wd >> 3, tI = wd & 3;
    return (rb * NKS + ks) * 32 + (rr & 7) * 4 + tI;
}
__device__ __forceinline__ int fragplane(int row, int wd) {
    return (((wd & 7) >= 4) ? 2 : 0) + (((row & 15) >= 8) ? 1 : 0);
}

__global__ __launch_bounds__(NTHREADS, 3) void mfvi_kernel(
    const float* __restrict__ unary,
    const float* __restrict__ mask,
    const float* __restrict__ Tg,
    const float* __restrict__ tstart,
    const float* __restrict__ tend,
    float* __restrict__ out)
{
    extern __shared__ char dsm_raw[];
    char* smp = (char*)(((uintptr_t)dsm_raw + 1023) & ~(uintptr_t)1023);
    uint32_t* AhiU = (uint32_t*)(smp + OFF_AHI);
    uint32_t* AloU = (uint32_t*)(smp + OFF_ALO);
    uint2*    BH   = (uint2*)   (smp + OFF_BH);
    float*    Msk  = (float*)   (smp + OFF_MSK);
    float*    Tss  = (float*)   (smp + OFF_TS);
    float*    Tes  = (float*)   (smp + OFF_TE);

    const int n    = blockIdx.y;
    const int p0   = blockIdx.x * TILE;
    const int base = p0 - 3;
    const int tid  = threadIdx.x;
    const int w    = tid >> 5;            // warp = row-block 0..7
    const int l    = tid & 31;
    const int gID  = l >> 2;
    const int tID  = l & 3;
    const int r    = 16 * w + gID;        // this lane's first row
    const int r8   = r + 8;               // second row
    const int ga   = base + r;
    const int gb   = base + r8;
    const bool vA  = (ga >= 0) && (ga < S_LEN);
    const bool vB  = (gb >= 0) && (gb < S_LEN);
    const float* uA = unary + ((size_t)n * S_LEN + (vA ? ga : 0)) * L;
    const float* uB = unary + ((size_t)n * S_LEN + (vB ? gb : 0)) * L;

    // ---- prologue: zero A hi+lo frag regions (never-written words must be 0) ----
    {
        float4 z = make_float4(0.f, 0.f, 0.f, 0.f);
        for (int i = tid; i < (int)(2 * 28672 / 16); i += NTHREADS)
            ((float4*)(smp + OFF_AHI))[i] = z;
    }
    // ---- B hi fragments (fp16), m16n8k16 col-major fragment order ----
    // B'[bn][k]: k<50 -> T[k][bn] ; 56<=k<106 -> T[bn][k-56] ; else 0
    for (int idx = tid; idx < 7 * NKS * 32; idx += NTHREADS) {
        int lane = idx & 31, rem = idx >> 5;
        int ks = rem % NKS, nt = rem / NKS;
        int gI = lane >> 2, tI = lane & 3;
        int bn = nt * 8 + gI;
        int k0 = 16 * ks + 2 * tI;
        float v[4];
        #pragma unroll
        for (int h = 0; h < 4; h++) {
            int k = k0 + (h >> 1) * 8 + (h & 1);
            float val = 0.f;
            if (bn < L) {
                if (k < L)                        val = Tg[k * L + bn];
                else if (k >= 56 && k < 56 + L)   val = Tg[bn * L + (k - 56)];
            }
            v[h] = val;
        }
        BH[(nt * NKS + ks) * 32 + lane] = make_uint2(hpack(v[0], v[1]), hpack(v[2], v[3]));
    }
    if (tid < RROWS) {
        int g = base + tid;
        Msk[tid] = (g >= 0 && g < S_LEN) ? mask[(size_t)n * S_LEN + g] : 0.f;
    }
    if (tid < 64) {
        Tss[tid] = (tid < L) ? tstart[tid] : 0.f;
        Tes[tid] = (tid < L) ? tend[tid]   : 0.f;
    }
    __syncthreads();

    float acc[7][4];   // [nt]: {row r c0, row r c1, row r8 c0, row r8 c1}

    #pragma unroll 1
    for (int it = 0; it <= 3; it++) {
        const bool actA = vA && (r  >= it) && (r  < RROWS - it);
        const bool actB = vB && (r8 >= it) && (r8 < RROWS - it);

        // ==== combine: acc = (u*m + D + bnd) * m   (acc holds D from last MMA) ====
        {
            const float ma = Msk[r], mb = Msk[r8];
            #pragma unroll
            for (int nt = 0; nt < 7; nt++) {
                const int c0 = 8 * nt + 2 * tID;
                if (c0 < L) {
                    float2 ua = vA ? *(const float2*)&uA[c0] : make_float2(0.f, 0.f);
                    float2 ub = vB ? *(const float2*)&uB[c0] : make_float2(0.f, 0.f);
                    if (it == 0) {
                        acc[nt][0] = ua.x * ma; acc[nt][1] = ua.y * ma;
                        acc[nt][2] = ub.x * mb; acc[nt][3] = ub.y * mb;
                    } else {
                        float2 ba = (ga == 0) ? *(const float2*)&Tss[c0]
                                              : *(const float2*)&Tes[c0];
                        float2 bb = *(const float2*)&Tes[c0];   // gb==0 impossible (r8>=8)
                        acc[nt][0] = (ua.x * ma + acc[nt][0] + ba.x) * ma;
                        acc[nt][1] = (ua.y * ma + acc[nt][1] + ba.y) * ma;
                        acc[nt][2] = (ub.x * mb + acc[nt][2] + bb.x) * mb;
                        acc[nt][3] = (ub.y * mb + acc[nt][3] + bb.y) * mb;
                    }
                }
            }
        }

        if (it == 3) {
            // ==== final write to global ====
            #pragma unroll
            for (int nt = 0; nt < 7; nt++) {
                const int c0 = 8 * nt + 2 * tID;
                if (c0 < L) {
                    if (actA)
                        *(float2*)&out[((size_t)n * S_LEN + ga) * L + c0] =
                            make_float2(acc[nt][0], acc[nt][1]);
                    if (actB)
                        *(float2*)&out[((size_t)n * S_LEN + gb) * L + c0] =
                            make_float2(acc[nt][2], acc[nt][3]);
                }
            }
            break;
        }

        // ==== softmax per row via quad shuffles ====
        {
            float mxa = -3.4e38f, mxb = -3.4e38f;
            #pragma unroll
            for (int nt = 0; nt < 7; nt++) {
                const int c0 = 8 * nt + 2 * tID;
                if (c0 < L) {
                    mxa = fmaxf(mxa, fmaxf(acc[nt][0], acc[nt][1]));
                    mxb = fmaxf(mxb, fmaxf(acc[nt][2], acc[nt][3]));
                }
            }
            mxa = fmaxf(mxa, __shfl_xor_sync(0xffffffffu, mxa, 1));
            mxb = fmaxf(mxb, __shfl_xor_sync(0xffffffffu, mxb, 1));
            mxa = fmaxf(mxa, __shfl_xor_sync(0xffffffffu, mxa, 2));
            mxb = fmaxf(mxb, __shfl_xor_sync(0xffffffffu, mxb, 2));
            float sa = 0.f, sb = 0.f;
            #pragma unroll
            for (int nt = 0; nt < 7; nt++) {
                const int c0 = 8 * nt + 2 * tID;
                if (c0 < L) {
                    acc[nt][0] = __expf(acc[nt][0] - mxa);
                    acc[nt][1] = __expf(acc[nt][1] - mxa);
                    acc[nt][2] = __expf(acc[nt][2] - mxb);
                    acc[nt][3] = __expf(acc[nt][3] - mxb);
                    sa += acc[nt][0] + acc[nt][1];
                    sb += acc[nt][2] + acc[nt][3];
                }
            }
            sa += __shfl_xor_sync(0xffffffffu, sa, 1);
            sb += __shfl_xor_sync(0xffffffffu, sb, 1);
            sa += __shfl_xor_sync(0xffffffffu, sa, 2);
            sb += __shfl_xor_sync(0xffffffffu, sb, 2);
            float ia = __fdividef(1.f, sa);
            float ib = __fdividef(1.f, sb);

            // ==== write A-fragments (hi/lo fp16, plane-split) for next MMA ====
            // left copy -> word 4nt+tID of row r+1 ; right copy -> word 28+4nt+tID of r-1
            #pragma unroll
            for (int nt = 0; nt < 7; nt++) {
                const int c0 = 8 * nt + 2 * tID;
                if (c0 < L) {
                    const int wd = 4 * nt + tID;
                    if (actA) {
                        float p0v = acc[nt][0] * ia, p1v = acc[nt][1] * ia;
                        uint32_t ph = hpack(p0v, p1v);
                        uint32_t pl = hpack(p0v - hhi(p0v), p1v - hhi(p1v));
                        if (r + 1 < RROWS) {
                            int ix = fragplane(r + 1, wd) * PLW + fragword(r + 1, wd);
                            AhiU[ix] = ph;  AloU[ix] = pl;
                        }
                        if (r - 1 >= 0) {
                            int ix = fragplane(r - 1, 28 + wd) * PLW
                                   + fragword(r - 1, 28 + wd);
                            AhiU[ix] = ph;  AloU[ix] = pl;
                        }
                    }
                    if (actB) {
                        float p0v = acc[nt][2] * ib, p1v = acc[nt][3] * ib;
                        uint32_t ph = hpack(p0v, p1v);
                        uint32_t pl = hpack(p0v - hhi(p0v), p1v - hhi(p1v));
                        if (r8 + 1 < RROWS) {
                            int ix = fragplane(r8 + 1, wd) * PLW + fragword(r8 + 1, wd);
                            AhiU[ix] = ph;  AloU[ix] = pl;
                        }
                        {                                   // r8-1 >= 7 always
                            int ix = fragplane(r8 - 1, 28 + wd) * PLW
                                   + fragword(r8 - 1, 28 + wd);
                            AhiU[ix] = ph;  AloU[ix] = pl;
                        }
                    }
                }
            }
        }
        __syncthreads();

        // ==== MMA: warp w = rows [16w,16w+16), all 7 col-groups, fp16 2-split ====
        {
            #pragma unroll
            for (int nt = 0; nt < 7; nt++)
                #pragma unroll
                for (int j = 0; j < 4; j++) acc[nt][j] = 0.f;

            #pragma unroll
            for (int ks = 0; ks < NKS; ks++) {
                const int wb = (w * NKS + ks) * 32 + l;
                // lane l's four frag components sit at word wb in planes 0..3
                uint32_t ha = AhiU[wb], hb = AhiU[PLW + wb];
                uint32_t hc = AhiU[2 * PLW + wb], hd = AhiU[3 * PLW + wb];
                uint32_t la = AloU[wb], lb = AloU[PLW + wb];
                uint32_t lc = AloU[2 * PLW + wb], ld = AloU[3 * PLW + wb];
                #pragma unroll
                for (int nt = 0; nt < 7; nt++) {
                    uint2 b = BH[(nt * NKS + ks) * 32 + l];
                    mma16(acc[nt], ha, hb, hc, hd, b.x, b.y);
                    mma16(acc[nt], la, lb, lc, ld, b.x, b.y);
                }
            }
        }
        __syncthreads();
    }
}

extern "C" void kernel_launch(void* const* d_in, const int* in_sizes, int n_in,
                              void* d_out, int out_size)
{
    const float* unary = (const float*)d_in[0];
    const float* mask  = (const float*)d_in[1];
    const float* T     = (const float*)d_in[2];
    const float* ts    = (const float*)d_in[3];
    const float* te    = (const float*)d_in[4];
    (void)n_in; (void)out_size;

    cudaFuncSetAttribute(mfvi_kernel,
                         cudaFuncAttributeMaxDynamicSharedMemorySize, SMEM_BYTES);

    int NS = in_sizes[1];
    int N  = NS / S_LEN;
    dim3 grid(NTILES, N);
    mfvi_kernel<<<grid, NTHREADS, SMEM_BYTES>>>(unary, mask, T, ts, te, (float*)d_out);
}

// round 17
// speedup vs baseline: 1.0260x; 1.0108x over previous
#include <cuda_runtime.h>
#include <cuda_fp16.h>
#include <cstdint>

#define S_LEN    2048
#define L        50
#define TILE     122
#define RROWS    128
#define NTHREADS 256
#define NTILES   ((S_LEN + TILE - 1) / TILE)   // 17

// K packing: left msg k 0..49, right msg k 56..105, K=112 (7 ks of 16)
#define NKS 7

// smem byte offsets
#define OFF_AH  0u          // A hi frags: 8 rb x 7 ks x 32 lanes x uint4 = 28672
#define OFF_BH  28672u      // B hi frags: 7 nt x 7 ks x 32 lanes x uint2 = 12544
#define OFF_MSK 41216u
#define OFF_TS  41728u
#define OFF_TE  41984u
#define SMEM_BYTES 42240

__device__ __forceinline__ uint32_t hpack(float e0, float e1) {
    uint32_t r;
    asm("cvt.rn.f16x2.f32 %0, %1, %2;" : "=r"(r) : "f"(e1), "f"(e0));
    return r;   // lower half = e0, upper = e1
}
__device__ __forceinline__ void mma16(float* d, uint32_t a0, uint32_t a1,
                                      uint32_t a2, uint32_t a3,
                                      uint32_t b0, uint32_t b1) {
    asm volatile(
        "mma.sync.aligned.m16n8k16.row.col.f32.f16.f16.f32 "
        "{%0,%1,%2,%3}, {%4,%5,%6,%7}, {%8,%9}, {%0,%1,%2,%3};"
        : "+f"(d[0]), "+f"(d[1]), "+f"(d[2]), "+f"(d[3])
        : "r"(a0), "r"(a1), "r"(a2), "r"(a3), "r"(b0), "r"(b1));
}

// word index (uint32) of A-fragment word (row, w); plain R14 layout
__device__ __forceinline__ int fragidx(int row, int w) {
    int rb = row >> 4, rr = row & 15;
    int ks = w >> 3, win = w & 7, tI = win & 3;
    int c = ((win >= 4) ? 2 : 0) + ((rr >= 8) ? 1 : 0);
    return (((rb * NKS + ks) * 32) + (rr & 7) * 4 + tI) * 4 + c;
}

__global__ __launch_bounds__(NTHREADS, 4) void mfvi_kernel(
    const float* __restrict__ unary,
    const float* __restrict__ mask,
    const float* __restrict__ Tg,
    const float* __restrict__ tstart,
    const float* __restrict__ tend,
    float* __restrict__ out)
{
    extern __shared__ char smp[];
    uint32_t* AhU = (uint32_t*)(smp + OFF_AH);
    uint2*    BH  = (uint2*)   (smp + OFF_BH);
    float*    Msk = (float*)   (smp + OFF_MSK);
    float*    Tss = (float*)   (smp + OFF_TS);
    float*    Tes = (float*)   (smp + OFF_TE);

    const int n    = blockIdx.y;
    const int p0   = blockIdx.x * TILE;
    const int base = p0 - 3;
    const int tid  = threadIdx.x;
    const int w    = tid >> 5;            // warp = row-block 0..7
    const int l    = tid & 31;
    const int gID  = l >> 2;
    const int tID  = l & 3;
    const int r    = 16 * w + gID;        // this lane's first row
    const int r8   = r + 8;               // second row
    const int ga   = base + r;
    const int gb   = base + r8;
    const bool vA  = (ga >= 0) && (ga < S_LEN);
    const bool vB  = (gb >= 0) && (gb < S_LEN);
    const float* uA = unary + ((size_t)n * S_LEN + (vA ? ga : 0)) * L;
    const float* uB = unary + ((size_t)n * S_LEN + (vB ? gb : 0)) * L;

    // ---- prologue: zero A frag region (never-written words must be 0) ----
    {
        float4 z = make_float4(0.f, 0.f, 0.f, 0.f);
        for (int i = tid; i < (int)(28672 / 16); i += NTHREADS)
            ((float4*)(smp + OFF_AH))[i] = z;
    }
    // ---- B hi fragments (fp16), m16n8k16 col-major fragment order ----
    // B'[bn][k]: k<50 -> T[k][bn] ; 56<=k<106 -> T[bn][k-56] ; else 0
    for (int idx = tid; idx < 7 * NKS * 32; idx += NTHREADS) {
        int lane = idx & 31, rem = idx >> 5;
        int ks = rem % NKS, nt = rem / NKS;
        int gI = lane >> 2, tI = lane & 3;
        int bn = nt * 8 + gI;
        int k0 = 16 * ks + 2 * tI;
        float v[4];
        #pragma unroll
        for (int h = 0; h < 4; h++) {
            int k = k0 + (h >> 1) * 8 + (h & 1);
            float val = 0.f;
            if (bn < L) {
                if (k < L)                        val = Tg[k * L + bn];
                else if (k >= 56 && k < 56 + L)   val = Tg[bn * L + (k - 56)];
            }
            v[h] = val;
        }
        BH[(nt * NKS + ks) * 32 + lane] = make_uint2(hpack(v[0], v[1]), hpack(v[2], v[3]));
    }
    if (tid < RROWS) {
        int g = base + tid;
        Msk[tid] = (g >= 0 && g < S_LEN) ? mask[(size_t)n * S_LEN + g] : 0.f;
    }
    if (tid < 64) {
        Tss[tid] = (tid < L) ? tstart[tid] : 0.f;
        Tes[tid] = (tid < L) ? tend[tid]   : 0.f;
    }
    __syncthreads();

    float acc[7][4];   // [nt]: {row r c0, row r c1, row r8 c0, row r8 c1}

    #pragma unroll 1
    for (int it = 0; it <= 3; it++) {
        const bool actA = vA && (r  >= it) && (r  < RROWS - it);
        const bool actB = vB && (r8 >= it) && (r8 < RROWS - it);

        // ==== combine: acc = (u*m + D + bnd) * m   (acc holds D from last MMA) ====
        {
            const float ma = Msk[r], mb = Msk[r8];
            #pragma unroll
            for (int nt = 0; nt < 7; nt++) {
                const int c0 = 8 * nt + 2 * tID;
                if (c0 < L) {
                    float2 ua = vA ? *(const float2*)&uA[c0] : make_float2(0.f, 0.f);
                    float2 ub = vB ? *(const float2*)&uB[c0] : make_float2(0.f, 0.f);
                    if (it == 0) {
                        acc[nt][0] = ua.x * ma; acc[nt][1] = ua.y * ma;
                        acc[nt][2] = ub.x * mb; acc[nt][3] = ub.y * mb;
                    } else {
                        float2 ba = (ga == 0) ? *(const float2*)&Tss[c0]
                                              : *(const float2*)&Tes[c0];
                        float2 bb = *(const float2*)&Tes[c0];   // gb==0 impossible (r8>=8)
                        acc[nt][0] = (ua.x * ma + acc[nt][0] + ba.x) * ma;
                        acc[nt][1] = (ua.y * ma + acc[nt][1] + ba.y) * ma;
                        acc[nt][2] = (ub.x * mb + acc[nt][2] + bb.x) * mb;
                        acc[nt][3] = (ub.y * mb + acc[nt][3] + bb.y) * mb;
                    }
                }
            }
        }

        if (it == 3) {
            // ==== final write to global ====
            #pragma unroll
            for (int nt = 0; nt < 7; nt++) {
                const int c0 = 8 * nt + 2 * tID;
                if (c0 < L) {
                    if (actA)
                        *(float2*)&out[((size_t)n * S_LEN + ga) * L + c0] =
                            make_float2(acc[nt][0], acc[nt][1]);
                    if (actB)
                        *(float2*)&out[((size_t)n * S_LEN + gb) * L + c0] =
                            make_float2(acc[nt][2], acc[nt][3]);
                }
            }
            break;
        }

        // ==== softmax per row via quad shuffles ====
        {
            float mxa = -3.4e38f, mxb = -3.4e38f;
            #pragma unroll
            for (int nt = 0; nt < 7; nt++) {
                const int c0 = 8 * nt + 2 * tID;
                if (c0 < L) {
                    mxa = fmaxf(mxa, fmaxf(acc[nt][0], acc[nt][1]));
                    mxb = fmaxf(mxb, fmaxf(acc[nt][2], acc[nt][3]));
                }
            }
            mxa = fmaxf(mxa, __shfl_xor_sync(0xffffffffu, mxa, 1));
            mxb = fmaxf(mxb, __shfl_xor_sync(0xffffffffu, mxb, 1));
            mxa = fmaxf(mxa, __shfl_xor_sync(0xffffffffu, mxa, 2));
            mxb = fmaxf(mxb, __shfl_xor_sync(0xffffffffu, mxb, 2));
            float sa = 0.f, sb = 0.f;
            #pragma unroll
            for (int nt = 0; nt < 7; nt++) {
                const int c0 = 8 * nt + 2 * tID;
                if (c0 < L) {
                    acc[nt][0] = __expf(acc[nt][0] - mxa);
                    acc[nt][1] = __expf(acc[nt][1] - mxa);
                    acc[nt][2] = __expf(acc[nt][2] - mxb);
                    acc[nt][3] = __expf(acc[nt][3] - mxb);
                    sa += acc[nt][0] + acc[nt][1];
                    sb += acc[nt][2] + acc[nt][3];
                }
            }
            sa += __shfl_xor_sync(0xffffffffu, sa, 1);
            sb += __shfl_xor_sync(0xffffffffu, sb, 1);
            sa += __shfl_xor_sync(0xffffffffu, sa, 2);
            sb += __shfl_xor_sync(0xffffffffu, sb, 2);
            float ia = __fdividef(1.f, sa);
            float ib = __fdividef(1.f, sb);

            // ==== write A-fragments (fp16 hi only) for next MMA ====
            // left copy -> word 4nt+tID of row r+1 ; right copy -> word 28+4nt+tID of r-1
            #pragma unroll
            for (int nt = 0; nt < 7; nt++) {
                const int c0 = 8 * nt + 2 * tID;
                if (c0 < L) {
                    const int wd = 4 * nt + tID;
                    if (actA) {
                        uint32_t ph = hpack(acc[nt][0] * ia, acc[nt][1] * ia);
                        if (r + 1 < RROWS) AhU[fragidx(r + 1, wd)] = ph;
                        if (r - 1 >= 0)    AhU[fragidx(r - 1, 28 + wd)] = ph;
                    }
                    if (actB) {
                        uint32_t ph = hpack(acc[nt][2] * ib, acc[nt][3] * ib);
                        if (r8 + 1 < RROWS) AhU[fragidx(r8 + 1, wd)] = ph;
                        AhU[fragidx(r8 - 1, 28 + wd)] = ph;   // r8-1 >= 7 always
                    }
                }
            }
        }
        __syncthreads();

        // ==== MMA: warp w = rows [16w,16w+16), all 7 col-groups, fp16 single ====
        {
            #pragma unroll
            for (int nt = 0; nt < 7; nt++)
                #pragma unroll
                for (int j = 0; j < 4; j++) acc[nt][j] = 0.f;

            const uint4* Ah4 = (const uint4*)(smp + OFF_AH);
            #pragma unroll
            for (int ks = 0; ks < NKS; ks++) {
                uint4 ah = Ah4[(w * NKS + ks) * 32 + l];
                #pragma unroll
                for (int nt = 0; nt < 7; nt++) {
                    uint2 b = BH[(nt * NKS + ks) * 32 + l];
                    mma16(acc[nt], ah.x, ah.y, ah.z, ah.w, b.x, b.y);
                }
            }
        }
        __syncthreads();
    }
}

extern "C" void kernel_launch(void* const* d_in, const int* in_sizes, int n_in,
                              void* d_out, int out_size)
{
    const float* unary = (const float*)d_in[0];
    const float* mask  = (const float*)d_in[1];
    const float* T     = (const float*)d_in[2];
    const float* ts    = (const float*)d_in[3];
    const float* te    = (const float*)d_in[4];
    (void)n_in; (void)out_size;

    cudaFuncSetAttribute(mfvi_kernel,
                         cudaFuncAttributeMaxDynamicSharedMemorySize, SMEM_BYTES);

    int NS = in_sizes[1];
    int N  = NS / S_LEN;
    dim3 grid(NTILES, N);
    mfvi_kernel<<<grid, NTHREADS, SMEM_BYTES>>>(unary, mask, T, ts, te, (float*)d_out);
}